// round 1
// baseline (speedup 1.0000x reference)
#include <cuda_runtime.h>

typedef unsigned long long u64;
typedef unsigned int u32;

#define NQ 22
#define DIM (1u << 22)

// Ping-pong state buffers (static device scratch — allowed per harness rules)
__device__ float2 g_buf0[DIM];
__device__ float2 g_buf1[DIM];
// Packed (broadcast f32x2) fused gate coefficients:
// per (layer,qubit): {u00r,u00i,-u00i, u01r,u01i,-u01i, u10r,u10i,-u10i, u11r,u11i,-u11i}
__device__ u64 g_gpk[4 * 22 * 12];
__device__ float g_norm;
__device__ float g_acc[NQ];

// ---------- packed f32x2 helpers (Blackwell: FFMA2 only reachable via PTX) ----------
__device__ __forceinline__ u64 pmul(u64 a, u64 b) {
    u64 d; asm("mul.rn.f32x2 %0, %1, %2;" : "=l"(d) : "l"(a), "l"(b)); return d;
}
__device__ __forceinline__ u64 pfma(u64 a, u64 b, u64 c) {
    u64 d; asm("fma.rn.f32x2 %0, %1, %2, %3;" : "=l"(d) : "l"(a), "l"(b), "l"(c)); return d;
}

// XOR swizzle on the packed-slot index (8B granules) -> <=2-way LDS conflicts in all phases
__device__ __forceinline__ u32 swz(u32 j) { return j ^ ((j >> 4) & 15u) ^ ((j >> 8) & 15u); }

// ---------- init / gate precompute / finalize ----------
__global__ void k_init() {
    if (threadIdx.x == 0) g_norm = 0.f;
    if (threadIdx.x < NQ) g_acc[threadIdx.x] = 0.f;
}

__global__ void k_gates(const float* __restrict__ P) {
    int t = threadIdx.x;
    if (t >= 88) return;  // t = l*22 + q
    float tx = P[t * 3 + 0], ty = P[t * 3 + 1], tz = P[t * 3 + 2];
    float cx = cosf(0.5f * tx), sx = sinf(0.5f * tx);
    float cy = cosf(0.5f * ty), sy = sinf(0.5f * ty);
    float cz = cosf(0.5f * tz), sz = sinf(0.5f * tz);
    // M = RY*RX  (RX=[[c,-is],[-is,c]], RY=[[cy,-sy],[sy,cy]])
    float m00r = cy * cx, m00i = sy * sx;
    float m01r = -sy * cx, m01i = -cy * sx;
    float m10r = sy * cx, m10i = -cy * sx;
    float m11r = cy * cx, m11i = -sy * sx;
    // U = RZ*M : row0 *= (cz,-sz), row1 *= (cz,+sz)
    float u00r = cz * m00r + sz * m00i, u00i = cz * m00i - sz * m00r;
    float u01r = cz * m01r + sz * m01i, u01i = cz * m01i - sz * m01r;
    float u10r = cz * m10r - sz * m10i, u10i = cz * m10i + sz * m10r;
    float u11r = cz * m11r - sz * m11i, u11i = cz * m11i + sz * m11r;
    float vals[12] = { u00r, u00i, -u00i, u01r, u01i, -u01i,
                       u10r, u10i, -u10i, u11r, u11i, -u11i };
    u64* W = g_gpk + t * 12;
#pragma unroll
    for (int i = 0; i < 12; i++) {
        u32 b = __float_as_uint(vals[i]);
        W[i] = ((u64)b << 32) | (u64)b;  // broadcast both lanes
    }
}

__global__ void k_final(float* __restrict__ out) {
    if (threadIdx.x < NQ) out[threadIdx.x] = g_acc[threadIdx.x] / g_norm;
}

// ---------- register-resident gate on bit G of the 4-bit register window ----------
template <int G>
__device__ __forceinline__ void gate_regs(u64* RE, u64* IM, const u64* __restrict__ W) {
    u64 p00r = W[0], p00i = W[1], n00i = W[2], p01r = W[3], p01i = W[4], n01i = W[5];
    u64 p10r = W[6], p10i = W[7], n10i = W[8], p11r = W[9], p11i = W[10], n11i = W[11];
#pragma unroll
    for (int h = 0; h < 8; h++) {
        const int m0 = ((h >> G) << (G + 1)) | (h & ((1 << G) - 1));
        const int m1 = m0 | (1 << G);
        u64 ar = RE[m0], ai = IM[m0], br = RE[m1], bi = IM[m1];
        u64 t0 = pmul(p00r, ar); t0 = pfma(n00i, ai, t0); t0 = pfma(p01r, br, t0); t0 = pfma(n01i, bi, t0);
        u64 t1 = pmul(p00i, ar); t1 = pfma(p00r, ai, t1); t1 = pfma(p01i, br, t1); t1 = pfma(p01r, bi, t1);
        u64 t2 = pmul(p10r, ar); t2 = pfma(n10i, ai, t2); t2 = pfma(p11r, br, t2); t2 = pfma(n11i, bi, t2);
        u64 t3 = pmul(p10i, ar); t3 = pfma(p10r, ai, t3); t3 = pfma(p11i, br, t3); t3 = pfma(p11r, bi, t3);
        RE[m0] = t0; IM[m0] = t1; RE[m1] = t2; IM[m1] = t3;
    }
}

__device__ __forceinline__ void load16(u64* RE, u64* IM, const float* s_re, const float* s_im,
                                       int tid, int s) {
#pragma unroll
    for (int m = 0; m < 16; m++) {
        u32 j = (((u32)tid >> s) << (s + 4)) | ((u32)m << s) | ((u32)tid & ((1u << s) - 1u));
        u32 pj = swz(j);
        RE[m] = *(const u64*)(s_re + 2 * pj);
        IM[m] = *(const u64*)(s_im + 2 * pj);
    }
}
__device__ __forceinline__ void store16(const u64* RE, const u64* IM, float* s_re, float* s_im,
                                        int tid, int s) {
#pragma unroll
    for (int m = 0; m < 16; m++) {
        u32 j = (((u32)tid >> s) << (s + 4)) | ((u32)m << s) | ((u32)tid & ((1u << s) - 1u));
        u32 pj = swz(j);
        *(u64*)(s_re + 2 * pj) = RE[m];
        *(u64*)(s_im + 2 * pj) = IM[m];
    }
}

// ---------- Pass A: gates on index bits 0..11 (wires 10..21). Tile = 8192 amps (bits 0..12),
// pack 2 amps along bit 12. layer>0: fused CNOT-chain permutation gather i = j ^ (j>>1). ----------
__global__ void __launch_bounds__(256) k_passA(const float* __restrict__ re_in,
                                               const float* __restrict__ im_in, int layer) {
    extern __shared__ float sm[];
    float* s_re = sm;          // 8192 floats: s_re[2*swz(j)+k] = Re(amp (k<<12)|j)
    float* s_im = sm + 8192;
    __shared__ float s_nrm[8];
    int tid = threadIdx.x;
    u32 base = (u32)blockIdx.x << 13;

    if (layer == 0) {
        float nrm = 0.f;
        for (int idx = tid; idx < 8192; idx += 256) {
            float r = re_in[base + idx], m = im_in[base + idx];
            u32 j = (u32)idx & 4095u, k = (u32)idx >> 12;
            u32 pj = swz(j);
            s_re[2 * pj + k] = r; s_im[2 * pj + k] = m;
            nrm += r * r + m * m;
        }
#pragma unroll
        for (int o = 16; o > 0; o >>= 1) nrm += __shfl_down_sync(0xffffffffu, nrm, o);
        if ((tid & 31) == 0) s_nrm[tid >> 5] = nrm;
    } else {
        for (int idx = tid; idx < 8192; idx += 256) {
            u32 gj = base + (u32)idx;
            u32 i = gj ^ (gj >> 1);  // inverse CNOT-chain permutation (binary->Gray)
            float2 v = g_buf1[i];
            u32 j = (u32)idx & 4095u, k = (u32)idx >> 12;
            u32 pj = swz(j);
            s_re[2 * pj + k] = v.x; s_im[2 * pj + k] = v.y;
        }
    }
    __syncthreads();
    if (layer == 0 && tid == 0) {
        float s = 0.f;
#pragma unroll
        for (int w = 0; w < 8; w++) s += s_nrm[w];
        atomicAdd(&g_norm, s);
    }

    const u64* Wb = g_gpk + layer * 22 * 12;
#pragma unroll
    for (int r = 0; r < 3; r++) {
        const int s = 4 * r;
        u64 RE[16], IM[16];
        load16(RE, IM, s_re, s_im, tid, s);
        gate_regs<0>(RE, IM, Wb + (21 - (s + 0)) * 12);  // bit p -> wire 21-p
        gate_regs<1>(RE, IM, Wb + (21 - (s + 1)) * 12);
        gate_regs<2>(RE, IM, Wb + (21 - (s + 2)) * 12);
        gate_regs<3>(RE, IM, Wb + (21 - (s + 3)) * 12);
        store16(RE, IM, s_re, s_im, tid, s);
        __syncthreads();
    }

    for (int idx = tid; idx < 8192; idx += 256) {
        u32 j = (u32)idx & 4095u, k = (u32)idx >> 12;
        u32 pj = swz(j);
        float2 v; v.x = s_re[2 * pj + k]; v.y = s_im[2 * pj + k];
        g_buf0[base + idx] = v;
    }
}

// ---------- Pass B core: gates on index bits 12..21 (wires 0..9).
// Tile = bits {12..21} + bits {0,1}; pack 2 amps along bit 0.
// Local L (12 bits): bits0..1 = global bits0..1, bits2..11 = global bits12..21.
// Packed slot e = L>>1 (11 bits): e-bit ge in 1..10 <-> global bit ge+11 <-> wire 10-ge. ----------
__device__ __forceinline__ void passB_core(int layer, float* s_re, float* s_im, int tid, u32 bb) {
    for (int li = tid; li < 4096; li += 128) {
        u32 L = (u32)li;
        u32 glob = ((L >> 2) << 12) | (bb << 2) | (L & 3u);
        float2 v = g_buf0[glob];
        u32 e = L >> 1, k = L & 1u;
        u32 pe = swz(e);
        s_re[2 * pe + k] = v.x; s_im[2 * pe + k] = v.y;
    }
    __syncthreads();
    const u64* Wb = g_gpk + layer * 22 * 12;
    u64 RE[16], IM[16];
    // round 0: window bits 0..3 of e; gate e-bits 1,2,3 -> wires 9,8,7 (e-bit 0 ungated)
    load16(RE, IM, s_re, s_im, tid, 0);
    gate_regs<1>(RE, IM, Wb + (10 - 1) * 12);
    gate_regs<2>(RE, IM, Wb + (10 - 2) * 12);
    gate_regs<3>(RE, IM, Wb + (10 - 3) * 12);
    store16(RE, IM, s_re, s_im, tid, 0);
    __syncthreads();
    // round 1: window bits 4..7; gate e-bits 4..7 -> wires 6,5,4,3
    load16(RE, IM, s_re, s_im, tid, 4);
    gate_regs<0>(RE, IM, Wb + (10 - 4) * 12);
    gate_regs<1>(RE, IM, Wb + (10 - 5) * 12);
    gate_regs<2>(RE, IM, Wb + (10 - 6) * 12);
    gate_regs<3>(RE, IM, Wb + (10 - 7) * 12);
    store16(RE, IM, s_re, s_im, tid, 4);
    __syncthreads();
    // round 2: window bits 7..10; gate e-bits 8,9,10 -> wires 2,1,0 (bit 7 already done)
    load16(RE, IM, s_re, s_im, tid, 7);
    gate_regs<1>(RE, IM, Wb + (10 - 8) * 12);
    gate_regs<2>(RE, IM, Wb + (10 - 9) * 12);
    gate_regs<3>(RE, IM, Wb + (10 - 10) * 12);
    store16(RE, IM, s_re, s_im, tid, 7);
    __syncthreads();
}

__global__ void __launch_bounds__(128) k_passB(int layer) {
    __shared__ float s_re[4096], s_im[4096];
    int tid = threadIdx.x; u32 bb = blockIdx.x;
    passB_core(layer, s_re, s_im, tid, bb);
    for (int li = tid; li < 4096; li += 128) {
        u32 L = (u32)li;
        u32 glob = ((L >> 2) << 12) | (bb << 2) | (L & 3u);
        u32 e = L >> 1, k = L & 1u, pe = swz(e);
        float2 v; v.x = s_re[2 * pe + k]; v.y = s_im[2 * pe + k];
        g_buf1[glob] = v;
    }
}

// Final pass B (layer 3): never write the state; fold the last CNOT permutation into the
// basis index and reduce <Z_q> directly.
__global__ void __launch_bounds__(128) k_passB_last() {
    __shared__ float s_re[4096], s_im[4096];
    __shared__ float s_part[NQ * 4];
    int tid = threadIdx.x; u32 bb = blockIdx.x;
    passB_core(3, s_re, s_im, tid, bb);

    float acc[NQ];
#pragma unroll
    for (int q = 0; q < NQ; q++) acc[q] = 0.f;
    for (int li = tid; li < 4096; li += 128) {
        u32 L = (u32)li;
        u32 glob = ((L >> 2) << 12) | (bb << 2) | (L & 3u);
        u32 e = L >> 1, k = L & 1u, pe = swz(e);
        float r = s_re[2 * pe + k], m = s_im[2 * pe + k];
        float p = r * r + m * m;
        u32 x = glob;  // apply final CNOT-chain permutation (suffix xor)
        x ^= x >> 1; x ^= x >> 2; x ^= x >> 4; x ^= x >> 8; x ^= x >> 16;
#pragma unroll
        for (int q = 0; q < NQ; q++)
            acc[q] += ((x >> (21 - q)) & 1u) ? -p : p;
    }
#pragma unroll
    for (int q = 0; q < NQ; q++) {
        float v = acc[q];
#pragma unroll
        for (int o = 16; o > 0; o >>= 1) v += __shfl_down_sync(0xffffffffu, v, o);
        if ((tid & 31) == 0) s_part[q * 4 + (tid >> 5)] = v;
    }
    __syncthreads();
    if (tid < NQ) {
        float s = s_part[tid * 4] + s_part[tid * 4 + 1] + s_part[tid * 4 + 2] + s_part[tid * 4 + 3];
        atomicAdd(&g_acc[tid], s);
    }
}

extern "C" void kernel_launch(void* const* d_in, const int* in_sizes, int n_in,
                              void* d_out, int out_size) {
    const float* params = (const float*)d_in[0];
    const float* sre = (const float*)d_in[1];
    const float* sim = (const float*)d_in[2];
    float* out = (float*)d_out;

    cudaFuncSetAttribute(k_passA, cudaFuncAttributeMaxDynamicSharedMemorySize, 65536);

    k_init<<<1, 32>>>();
    k_gates<<<1, 96>>>(params);
    for (int l = 0; l < 4; l++) {
        k_passA<<<512, 256, 65536>>>(sre, sim, l);
        if (l < 3) k_passB<<<1024, 128>>>(l);
        else       k_passB_last<<<1024, 128>>>();
    }
    k_final<<<1, 32>>>(out);
}

// round 2
// speedup vs baseline: 1.0528x; 1.0528x over previous
#include <cuda_runtime.h>

typedef unsigned long long u64;
typedef unsigned int u32;

#define NQ 22
#define DIM (1u << 22)

// Ping-pong state buffers (static device scratch)
__device__ float2 g_buf0[DIM];
__device__ float2 g_buf1[DIM];
// Packed (broadcast f32x2) fused gate coefficients:
// per (layer,qubit): {u00r,u00i,-u00i, u01r,u01i,-u01i, u10r,u10i,-u10i, u11r,u11i,-u11i}
__device__ u64 g_gpk[4 * 22 * 12];
__device__ float g_norm;
__device__ float g_acc[NQ];

// ---------- packed f32x2 helpers ----------
__device__ __forceinline__ u64 pmul(u64 a, u64 b) {
    u64 d; asm("mul.rn.f32x2 %0, %1, %2;" : "=l"(d) : "l"(a), "l"(b)); return d;
}
__device__ __forceinline__ u64 pfma(u64 a, u64 b, u64 c) {
    u64 d; asm("fma.rn.f32x2 %0, %1, %2, %3;" : "=l"(d) : "l"(a), "l"(b), "l"(c)); return d;
}
__device__ __forceinline__ u64 pk2(float lo, float hi) {
    return ((u64)__float_as_uint(hi) << 32) | (u64)__float_as_uint(lo);
}
__device__ __forceinline__ float plo(u64 v) { return __uint_as_float((u32)v); }
__device__ __forceinline__ float phi(u64 v) { return __uint_as_float((u32)(v >> 32)); }

// XOR swizzle on packed-slot index (8B granules); XOR-linear so per-slot offsets are constexpr
__host__ __device__ constexpr u32 swz(u32 j) { return j ^ ((j >> 4) & 15u) ^ ((j >> 8) & 15u); }

// ---------- gate precompute (+ accumulator init folded in) ----------
__global__ void k_gates(const float* __restrict__ P) {
    int t = threadIdx.x;
    if (t < NQ) g_acc[t] = 0.f;
    if (t == NQ) g_norm = 0.f;
    if (t >= 88) return;  // t = l*22 + q
    float tx = P[t * 3 + 0], ty = P[t * 3 + 1], tz = P[t * 3 + 2];
    float cx = cosf(0.5f * tx), sx = sinf(0.5f * tx);
    float cy = cosf(0.5f * ty), sy = sinf(0.5f * ty);
    float cz = cosf(0.5f * tz), sz = sinf(0.5f * tz);
    float m00r = cy * cx, m00i = sy * sx;
    float m01r = -sy * cx, m01i = -cy * sx;
    float m10r = sy * cx, m10i = -cy * sx;
    float m11r = cy * cx, m11i = -sy * sx;
    float u00r = cz * m00r + sz * m00i, u00i = cz * m00i - sz * m00r;
    float u01r = cz * m01r + sz * m01i, u01i = cz * m01i - sz * m01r;
    float u10r = cz * m10r - sz * m10i, u10i = cz * m10i + sz * m10r;
    float u11r = cz * m11r - sz * m11i, u11i = cz * m11i + sz * m11r;
    float vals[12] = { u00r, u00i, -u00i, u01r, u01i, -u01i,
                       u10r, u10i, -u10i, u11r, u11i, -u11i };
    u64* W = g_gpk + t * 12;
#pragma unroll
    for (int i = 0; i < 12; i++) {
        u32 b = __float_as_uint(vals[i]);
        W[i] = ((u64)b << 32) | (u64)b;
    }
}

__global__ void k_final(float* __restrict__ out) {
    if (threadIdx.x < NQ) out[threadIdx.x] = g_acc[threadIdx.x] / g_norm;
}

// ---------- register-resident gate on bit G of the 4-bit register window ----------
template <int G>
__device__ __forceinline__ void gate_regs(u64* RE, u64* IM, const u64* __restrict__ W) {
    u64 p00r = W[0], p00i = W[1], n00i = W[2], p01r = W[3], p01i = W[4], n01i = W[5];
    u64 p10r = W[6], p10i = W[7], n10i = W[8], p11r = W[9], p11i = W[10], n11i = W[11];
#pragma unroll
    for (int h = 0; h < 8; h++) {
        const int m0 = ((h >> G) << (G + 1)) | (h & ((1 << G) - 1));
        const int m1 = m0 | (1 << G);
        u64 ar = RE[m0], ai = IM[m0], br = RE[m1], bi = IM[m1];
        u64 t0 = pmul(p00r, ar); t0 = pfma(n00i, ai, t0); t0 = pfma(p01r, br, t0); t0 = pfma(n01i, bi, t0);
        u64 t1 = pmul(p00i, ar); t1 = pfma(p00r, ai, t1); t1 = pfma(p01i, br, t1); t1 = pfma(p01r, bi, t1);
        u64 t2 = pmul(p10r, ar); t2 = pfma(n10i, ai, t2); t2 = pfma(p11r, br, t2); t2 = pfma(n11i, bi, t2);
        u64 t3 = pmul(p10i, ar); t3 = pfma(p10r, ai, t3); t3 = pfma(p11i, br, t3); t3 = pfma(p11r, bi, t3);
        RE[m0] = t0; IM[m0] = t1; RE[m1] = t2; IM[m1] = t3;
    }
}

// ---------- smem load/store of a 16-slot register window, XOR-linear addressing ----------
// smem layout: u64 slot e lives at byte offset swz(e)*8 in s_re; s_im is s_re + IMOFF bytes.
template <int S, int IMOFF>
__device__ __forceinline__ void lds16(u64* RE, u64* IM, const char* s_base, int tid) {
    u32 tp = (((u32)tid >> S) << (S + 4)) | ((u32)tid & ((1u << S) - 1u));
    u32 tb = swz(tp) * 8u;
#pragma unroll
    for (int m = 0; m < 16; m++) {
        u32 a = tb ^ (swz((u32)m << S) * 8u);
        RE[m] = *(const u64*)(s_base + a);
        IM[m] = *(const u64*)(s_base + a + IMOFF);
    }
}
template <int S, int IMOFF>
__device__ __forceinline__ void sts16(const u64* RE, const u64* IM, char* s_base, int tid) {
    u32 tp = (((u32)tid >> S) << (S + 4)) | ((u32)tid & ((1u << S) - 1u));
    u32 tb = swz(tp) * 8u;
#pragma unroll
    for (int m = 0; m < 16; m++) {
        u32 a = tb ^ (swz((u32)m << S) * 8u);
        *(u64*)(s_base + a) = RE[m];
        *(u64*)(s_base + a + IMOFF) = IM[m];
    }
}

// ---------- Pass A: gates on index bits 0..11 (wires 10..21). Tile = 8192 amps
// (glob bits 0..12 + block base), packed along bit 12. Round order: 8-11 (direct gmem
// load), 0-3 (smem), 4-7 (smem, direct gmem store). layer>0 gathers through the fused
// CNOT-chain permutation i = g ^ (g>>1). ----------
__global__ void __launch_bounds__(256) k_passA(const float* __restrict__ re_in,
                                               const float* __restrict__ im_in, int layer) {
    extern __shared__ float sm[];          // 64KB: s_re[8192 B slots*8] then s_im
    char* s_base = (char*)sm;
    const int IMOFF = 32768;
    __shared__ float s_nrm[8];
    int tid = threadIdx.x;
    u32 base = (u32)blockIdx.x << 13;
    const u64* Wb = g_gpk + layer * 22 * 12;

    u64 RE[16], IM[16];
    // ---- round 0: direct load (S=8 window: slot j = m<<8 | tid), gate bits 8..11 ----
    if (layer == 0) {
        u64 nacc = 0;
#pragma unroll
        for (int m = 0; m < 16; m++) {
            u32 a0 = base | ((u32)m << 8) | (u32)tid;
            u32 a1 = a0 | 4096u;
            float r0 = re_in[a0], i0 = im_in[a0], r1 = re_in[a1], i1 = im_in[a1];
            RE[m] = pk2(r0, r1); IM[m] = pk2(i0, i1);
            nacc = pfma(RE[m], RE[m], nacc);
            nacc = pfma(IM[m], IM[m], nacc);
        }
        float nrm = plo(nacc) + phi(nacc);
#pragma unroll
        for (int o = 16; o > 0; o >>= 1) nrm += __shfl_down_sync(0xffffffffu, nrm, o);
        if ((tid & 31) == 0) s_nrm[tid >> 5] = nrm;
    } else {
#pragma unroll
        for (int m = 0; m < 16; m++) {
            u32 g0 = base | ((u32)m << 8) | (u32)tid;
            u32 a0 = g0 ^ (g0 >> 1);         // binary->Gray (inverse CNOT chain)
            u32 a1 = a0 ^ 6144u;             // partner amp (bit 12 flipped pre-perm)
            float2 v0 = g_buf1[a0], v1 = g_buf1[a1];
            RE[m] = pk2(v0.x, v1.x); IM[m] = pk2(v0.y, v1.y);
        }
    }
    gate_regs<0>(RE, IM, Wb + (21 - 8) * 12);
    gate_regs<1>(RE, IM, Wb + (21 - 9) * 12);
    gate_regs<2>(RE, IM, Wb + (21 - 10) * 12);
    gate_regs<3>(RE, IM, Wb + (21 - 11) * 12);
    sts16<8, IMOFF>(RE, IM, s_base, tid);
    __syncthreads();
    if (layer == 0 && tid == 0) {
        float s = 0.f;
#pragma unroll
        for (int w = 0; w < 8; w++) s += s_nrm[w];
        atomicAdd(&g_norm, s);
    }

    // ---- round 1: S=0 window, gate bits 0..3 ----
    lds16<0, IMOFF>(RE, IM, s_base, tid);
    gate_regs<0>(RE, IM, Wb + (21 - 0) * 12);
    gate_regs<1>(RE, IM, Wb + (21 - 1) * 12);
    gate_regs<2>(RE, IM, Wb + (21 - 2) * 12);
    gate_regs<3>(RE, IM, Wb + (21 - 3) * 12);
    sts16<0, IMOFF>(RE, IM, s_base, tid);
    __syncthreads();

    // ---- round 2: S=4 window, gate bits 4..7, direct coalesced store ----
    lds16<4, IMOFF>(RE, IM, s_base, tid);
    gate_regs<0>(RE, IM, Wb + (21 - 4) * 12);
    gate_regs<1>(RE, IM, Wb + (21 - 5) * 12);
    gate_regs<2>(RE, IM, Wb + (21 - 6) * 12);
    gate_regs<3>(RE, IM, Wb + (21 - 7) * 12);
    {
        u32 tp = (((u32)tid >> 4) << 8) | ((u32)tid & 15u);
#pragma unroll
        for (int m = 0; m < 16; m++) {
            u32 j = tp | ((u32)m << 4);
            u32 a0 = base | j;
            float2 v0; v0.x = plo(RE[m]); v0.y = plo(IM[m]);
            float2 v1; v1.x = phi(RE[m]); v1.y = phi(IM[m]);
            g_buf0[a0] = v0;
            g_buf0[a0 | 4096u] = v1;
        }
    }
}

// ---------- Pass B: gates on glob bits 12..21 (wires 0..9). Tile = glob bits {12..21,0,1},
// packed along glob bit 0. Slot e (11 bits): e-bit0 = glob bit1, e-bits 1..10 = glob 12..21.
// Round order: e4-7 (direct LDG.128), e1-3 (smem), e8-10 (smem, direct STG.128). ----------
__device__ __forceinline__ u32 globOf(u32 e, u32 bb) {
    return ((e >> 1) << 12) | (bb << 2) | ((e & 1u) << 1);
}

template <int LAST>
__device__ __forceinline__ void passB_body(int layer, char* s_base, int tid, u32 bb,
                                           u64* RE, u64* IM) {
    const int IMOFF = 16384;
    const u64* Wb = g_gpk + layer * 22 * 12;
    // ---- round 0: direct load, S=4 window (e = tp | m<<4), gate e-bits 4..7 ----
    {
        u32 tp = (((u32)tid >> 4) << 8) | ((u32)tid & 15u);
        u32 Gtp = globOf(tp, bb);
#pragma unroll
        for (int m = 0; m < 16; m++) {
            const float4* p = (const float4*)&g_buf0[Gtp + ((u32)m << 15)];
            float4 v = *p;
            RE[m] = pk2(v.x, v.z); IM[m] = pk2(v.y, v.w);
        }
    }
    gate_regs<0>(RE, IM, Wb + (10 - 4) * 12);
    gate_regs<1>(RE, IM, Wb + (10 - 5) * 12);
    gate_regs<2>(RE, IM, Wb + (10 - 6) * 12);
    gate_regs<3>(RE, IM, Wb + (10 - 7) * 12);
    sts16<4, IMOFF>(RE, IM, s_base, tid);
    __syncthreads();
    // ---- round 1: S=0 window, gate e-bits 1..3 ----
    lds16<0, IMOFF>(RE, IM, s_base, tid);
    gate_regs<1>(RE, IM, Wb + (10 - 1) * 12);
    gate_regs<2>(RE, IM, Wb + (10 - 2) * 12);
    gate_regs<3>(RE, IM, Wb + (10 - 3) * 12);
    sts16<0, IMOFF>(RE, IM, s_base, tid);
    __syncthreads();
    // ---- round 2: S=7 window (e = m<<7 | tid), gate e-bits 8..10 ----
    lds16<7, IMOFF>(RE, IM, s_base, tid);
    gate_regs<1>(RE, IM, Wb + (10 - 8) * 12);
    gate_regs<2>(RE, IM, Wb + (10 - 9) * 12);
    gate_regs<3>(RE, IM, Wb + (10 - 10) * 12);
    if (!LAST) {
        u32 Gt = globOf((u32)tid, bb);
#pragma unroll
        for (int m = 0; m < 16; m++) {
            float4 v; v.x = plo(RE[m]); v.y = plo(IM[m]); v.z = phi(RE[m]); v.w = phi(IM[m]);
            *(float4*)&g_buf1[Gt + ((u32)m << 18)] = v;  // e=m<<7|tid -> glob stride m<<18
        }
    }
}

__global__ void __launch_bounds__(128) k_passB(int layer) {
    __shared__ float smem[8192];   // 32KB
    u64 RE[16], IM[16];
    passB_body<0>(layer, (char*)smem, threadIdx.x, blockIdx.x, RE, IM);
}

// Final pass B (layer 3): fold the last CNOT permutation into the basis index and
// reduce <Z_q> directly; final state is never written.
__global__ void __launch_bounds__(128) k_passB_last() {
    __shared__ float smem[8192];
    __shared__ float s_part[NQ * 4];
    int tid = threadIdx.x; u32 bb = blockIdx.x;
    u64 RE[16], IM[16];
    passB_body<1>(3, (char*)smem, tid, bb, RE, IM);

    float acc[NQ];
#pragma unroll
    for (int q = 0; q < NQ; q++) acc[q] = 0.f;
    u32 Gt = globOf((u32)tid, bb);
#pragma unroll
    for (int m = 0; m < 16; m++) {
        u64 P = pfma(RE[m], RE[m], pmul(IM[m], IM[m]));   // (p0, p1) packed
        float p0 = plo(P), p1 = phi(P);
        float s = p0 + p1, d = p0 - p1;
        u32 G = Gt + ((u32)m << 18);
        u32 x = G;                  // forward CNOT-chain permutation (suffix xor)
        x ^= x >> 1; x ^= x >> 2; x ^= x >> 4; x ^= x >> 8; x ^= x >> 16;
#pragma unroll
        for (int q = 0; q < 21; q++)
            acc[q] += ((x >> (21 - q)) & 1u) ? -s : s;
        acc[21] += (x & 1u) ? -d : d;   // partner amp has x^1: wire-21 sign flips
    }
#pragma unroll
    for (int q = 0; q < NQ; q++) {
        float v = acc[q];
#pragma unroll
        for (int o = 16; o > 0; o >>= 1) v += __shfl_down_sync(0xffffffffu, v, o);
        if ((tid & 31) == 0) s_part[q * 4 + (tid >> 5)] = v;
    }
    __syncthreads();
    if (tid < NQ) {
        float s = s_part[tid * 4] + s_part[tid * 4 + 1] + s_part[tid * 4 + 2] + s_part[tid * 4 + 3];
        atomicAdd(&g_acc[tid], s);
    }
}

extern "C" void kernel_launch(void* const* d_in, const int* in_sizes, int n_in,
                              void* d_out, int out_size) {
    const float* params = (const float*)d_in[0];
    const float* sre = (const float*)d_in[1];
    const float* sim = (const float*)d_in[2];
    float* out = (float*)d_out;

    cudaFuncSetAttribute(k_passA, cudaFuncAttributeMaxDynamicSharedMemorySize, 65536);

    k_gates<<<1, 128>>>(params);
    for (int l = 0; l < 4; l++) {
        k_passA<<<512, 256, 65536>>>(sre, sim, l);
        if (l < 3) k_passB<<<1024, 128>>>(l);
        else       k_passB_last<<<1024, 128>>>();
    }
    k_final<<<1, 32>>>(out);
}

// round 5
// speedup vs baseline: 1.2318x; 1.1700x over previous
#include <cuda_runtime.h>

typedef unsigned long long u64;
typedef unsigned int u32;

#define NQ 22
#define DIM (1u << 22)

// Ping-pong state buffers (static device scratch)
__device__ float2 g_buf0[DIM];
__device__ float2 g_buf1[DIM];
// Packed (broadcast f32x2) fused gate coefficients:
// per (layer,qubit): {u00r,u00i,-u00i, u01r,u01i,-u01i, u10r,u10i,-u10i, u11r,u11i,-u11i}
__device__ u64 g_gpk[4 * 22 * 12];
__device__ float g_norm;
__device__ float g_acc[NQ];

// ---------- packed f32x2 helpers ----------
__device__ __forceinline__ u64 pmul(u64 a, u64 b) {
    u64 d; asm("mul.rn.f32x2 %0, %1, %2;" : "=l"(d) : "l"(a), "l"(b)); return d;
}
__device__ __forceinline__ u64 pfma(u64 a, u64 b, u64 c) {
    u64 d; asm("fma.rn.f32x2 %0, %1, %2, %3;" : "=l"(d) : "l"(a), "l"(b), "l"(c)); return d;
}
__device__ __forceinline__ u64 pk2(float lo, float hi) {
    return ((u64)__float_as_uint(hi) << 32) | (u64)__float_as_uint(lo);
}
__device__ __forceinline__ float plo(u64 v) { return __uint_as_float((u32)v); }
__device__ __forceinline__ float phi(u64 v) { return __uint_as_float((u32)(v >> 32)); }

// XOR swizzle on packed-slot index (8B granules); XOR-linear so per-slot offsets are constexpr
__host__ __device__ constexpr u32 swz(u32 j) { return j ^ ((j >> 4) & 15u) ^ ((j >> 8) & 15u); }

// ---------- gate precompute (+ accumulator init folded in) ----------
__global__ void k_gates(const float* __restrict__ P) {
    int t = threadIdx.x;
    if (t < NQ) g_acc[t] = 0.f;
    if (t == NQ) g_norm = 0.f;
    if (t >= 88) return;  // t = l*22 + q
    float tx = P[t * 3 + 0], ty = P[t * 3 + 1], tz = P[t * 3 + 2];
    float cx = cosf(0.5f * tx), sx = sinf(0.5f * tx);
    float cy = cosf(0.5f * ty), sy = sinf(0.5f * ty);
    float cz = cosf(0.5f * tz), sz = sinf(0.5f * tz);
    float m00r = cy * cx, m00i = sy * sx;
    float m01r = -sy * cx, m01i = -cy * sx;
    float m10r = sy * cx, m10i = -cy * sx;
    float m11r = cy * cx, m11i = -sy * sx;
    float u00r = cz * m00r + sz * m00i, u00i = cz * m00i - sz * m00r;
    float u01r = cz * m01r + sz * m01i, u01i = cz * m01i - sz * m01r;
    float u10r = cz * m10r - sz * m10i, u10i = cz * m10i + sz * m10r;
    float u11r = cz * m11r - sz * m11i, u11i = cz * m11i + sz * m11r;
    float vals[12] = { u00r, u00i, -u00i, u01r, u01i, -u01i,
                       u10r, u10i, -u10i, u11r, u11i, -u11i };
    u64* W = g_gpk + t * 12;
#pragma unroll
    for (int i = 0; i < 12; i++) {
        u32 b = __float_as_uint(vals[i]);
        W[i] = ((u64)b << 32) | (u64)b;
    }
}

__global__ void k_final(float* __restrict__ out) {
    if (threadIdx.x < NQ) out[threadIdx.x] = g_acc[threadIdx.x] / g_norm;
}

// ---------- register-resident gate on bit G of the 4-bit register window ----------
// W points into the block's shared-memory gate table (LDS broadcast, not LDG).
template <int G>
__device__ __forceinline__ void gate_regs(u64* RE, u64* IM, const u64* W) {
    u64 p00r = W[0], p00i = W[1], n00i = W[2], p01r = W[3], p01i = W[4], n01i = W[5];
    u64 p10r = W[6], p10i = W[7], n10i = W[8], p11r = W[9], p11i = W[10], n11i = W[11];
#pragma unroll
    for (int h = 0; h < 8; h++) {
        const int m0 = ((h >> G) << (G + 1)) | (h & ((1 << G) - 1));
        const int m1 = m0 | (1 << G);
        u64 ar = RE[m0], ai = IM[m0], br = RE[m1], bi = IM[m1];
        u64 t0 = pmul(p00r, ar); t0 = pfma(n00i, ai, t0); t0 = pfma(p01r, br, t0); t0 = pfma(n01i, bi, t0);
        u64 t1 = pmul(p00i, ar); t1 = pfma(p00r, ai, t1); t1 = pfma(p01i, br, t1); t1 = pfma(p01r, bi, t1);
        u64 t2 = pmul(p10r, ar); t2 = pfma(n10i, ai, t2); t2 = pfma(p11r, br, t2); t2 = pfma(n11i, bi, t2);
        u64 t3 = pmul(p10i, ar); t3 = pfma(p10r, ai, t3); t3 = pfma(p11i, br, t3); t3 = pfma(p11r, bi, t3);
        RE[m0] = t0; IM[m0] = t1; RE[m1] = t2; IM[m1] = t3;
    }
}

// ---------- smem load/store of a 16-slot register window, XOR-linear addressing ----------
template <int S, int IMOFF>
__device__ __forceinline__ void lds16(u64* RE, u64* IM, const char* s_base, int tid) {
    u32 tp = (((u32)tid >> S) << (S + 4)) | ((u32)tid & ((1u << S) - 1u));
    u32 tb = swz(tp) * 8u;
#pragma unroll
    for (int m = 0; m < 16; m++) {
        u32 a = tb ^ (swz((u32)m << S) * 8u);
        RE[m] = *(const u64*)(s_base + a);
        IM[m] = *(const u64*)(s_base + a + IMOFF);
    }
}
template <int S, int IMOFF>
__device__ __forceinline__ void sts16(const u64* RE, const u64* IM, char* s_base, int tid) {
    u32 tp = (((u32)tid >> S) << (S + 4)) | ((u32)tid & ((1u << S) - 1u));
    u32 tb = swz(tp) * 8u;
#pragma unroll
    for (int m = 0; m < 16; m++) {
        u32 a = tb ^ (swz((u32)m << S) * 8u);
        *(u64*)(s_base + a) = RE[m];
        *(u64*)(s_base + a + IMOFF) = IM[m];
    }
}

// ---------- shared rounds 1+2 of pass A (gate bits 0..7, store round fused to gmem) ----------
__device__ __forceinline__ void passA_tail(char* s_base, const u64* sg, int tid, u32 base) {
    const int IMOFF = 32768;
    u64 RE[16], IM[16];
    // round 1: S=0 window, gate bits 0..3 (wires 21..18)
    lds16<0, IMOFF>(RE, IM, s_base, tid);
    gate_regs<0>(RE, IM, sg + (21 - 0) * 12);
    gate_regs<1>(RE, IM, sg + (21 - 1) * 12);
    gate_regs<2>(RE, IM, sg + (21 - 2) * 12);
    gate_regs<3>(RE, IM, sg + (21 - 3) * 12);
    sts16<0, IMOFF>(RE, IM, s_base, tid);
    __syncthreads();
    // round 2: S=4 window, gate bits 4..7, direct coalesced store
    lds16<4, IMOFF>(RE, IM, s_base, tid);
    gate_regs<0>(RE, IM, sg + (21 - 4) * 12);
    gate_regs<1>(RE, IM, sg + (21 - 5) * 12);
    gate_regs<2>(RE, IM, sg + (21 - 6) * 12);
    gate_regs<3>(RE, IM, sg + (21 - 7) * 12);
    u32 tp = (((u32)tid >> 4) << 8) | ((u32)tid & 15u);
#pragma unroll
    for (int m = 0; m < 16; m++) {
        u32 a0 = base | tp | ((u32)m << 4);
        float2 v0; v0.x = plo(RE[m]); v0.y = plo(IM[m]);
        float2 v1; v1.x = phi(RE[m]); v1.y = phi(IM[m]);
        g_buf0[a0] = v0;
        g_buf0[a0 | 4096u] = v1;
    }
}

// ---------- Pass A, layer 0: reads the raw input state, accumulates the norm ----------
__global__ void __launch_bounds__(256, 2) k_passA0(const float* __restrict__ re_in,
                                                   const float* __restrict__ im_in) {
    extern __shared__ float sm[];          // 64KB state tile
    __shared__ u64 s_gate[264];
    __shared__ float s_nrm[8];
    char* s_base = (char*)sm;
    const int IMOFF = 32768;
    int tid = threadIdx.x;
    u32 base = (u32)blockIdx.x << 13;

    for (int i = tid; i < 264; i += 256) s_gate[i] = g_gpk[i];  // layer 0

    u64 RE[16], IM[16];
    u64 nacc = 0;
#pragma unroll
    for (int m = 0; m < 16; m++) {
        u32 a0 = base | ((u32)m << 8) | (u32)tid;
        u32 a1 = a0 | 4096u;
        float r0 = re_in[a0], i0 = im_in[a0], r1 = re_in[a1], i1 = im_in[a1];
        RE[m] = pk2(r0, r1); IM[m] = pk2(i0, i1);
        nacc = pfma(RE[m], RE[m], nacc);
        nacc = pfma(IM[m], IM[m], nacc);
    }
    float nrm = plo(nacc) + phi(nacc);
#pragma unroll
    for (int o = 16; o > 0; o >>= 1) nrm += __shfl_down_sync(0xffffffffu, nrm, o);
    if ((tid & 31) == 0) s_nrm[tid >> 5] = nrm;
    __syncthreads();  // coefficient + norm stores visible
    if (tid == 0) {
        float s = 0.f;
#pragma unroll
        for (int w = 0; w < 8; w++) s += s_nrm[w];
        atomicAdd(&g_norm, s);
    }
    gate_regs<0>(RE, IM, s_gate + (21 - 8) * 12);
    gate_regs<1>(RE, IM, s_gate + (21 - 9) * 12);
    gate_regs<2>(RE, IM, s_gate + (21 - 10) * 12);
    gate_regs<3>(RE, IM, s_gate + (21 - 11) * 12);
    sts16<8, IMOFF>(RE, IM, s_base, tid);
    __syncthreads();
    passA_tail(s_base, s_gate, tid, base);
}

// ---------- Pass A, layers 1..3: gathers through the fused CNOT permutation ----------
__global__ void __launch_bounds__(256, 2) k_passAg(int layer) {
    extern __shared__ float sm[];
    __shared__ u64 s_gate[264];
    char* s_base = (char*)sm;
    const int IMOFF = 32768;
    int tid = threadIdx.x;
    u32 base = (u32)blockIdx.x << 13;

    for (int i = tid; i < 264; i += 256) s_gate[i] = g_gpk[layer * 264 + i];

    u64 RE[16], IM[16];
#pragma unroll
    for (int m = 0; m < 16; m++) {
        u32 g0 = base | ((u32)m << 8) | (u32)tid;
        u32 a0 = g0 ^ (g0 >> 1);         // binary->Gray (inverse CNOT chain)
        u32 a1 = a0 ^ 6144u;             // partner amp (bit 12 flipped pre-perm)
        float2 v0 = g_buf1[a0], v1 = g_buf1[a1];
        RE[m] = pk2(v0.x, v1.x); IM[m] = pk2(v0.y, v1.y);
    }
    __syncthreads();  // coefficient stores visible
    gate_regs<0>(RE, IM, s_gate + (21 - 8) * 12);
    gate_regs<1>(RE, IM, s_gate + (21 - 9) * 12);
    gate_regs<2>(RE, IM, s_gate + (21 - 10) * 12);
    gate_regs<3>(RE, IM, s_gate + (21 - 11) * 12);
    sts16<8, IMOFF>(RE, IM, s_base, tid);
    __syncthreads();
    passA_tail(s_base, s_gate, tid, base);
}

// ---------- Pass B: gates on glob bits 12..21 (wires 0..9). Tile = glob bits {12..21,0,1},
// packed along glob bit 0. Slot e (11 bits): e-bit0 = glob bit1, e-bits 1..10 = glob 12..21. ----------
__device__ __forceinline__ u32 globOf(u32 e, u32 bb) {
    return ((e >> 1) << 12) | (bb << 2) | ((e & 1u) << 1);
}

template <int LAST>
__device__ __forceinline__ void passB_body(int layer, char* s_base, u64* s_gate, int tid, u32 bb,
                                           u64* RE, u64* IM) {
    const int IMOFF = 16384;
    for (int i = tid; i < 264; i += 128) s_gate[i] = g_gpk[layer * 264 + i];
    // ---- round 0: direct load, S=4 window (e = tp | m<<4), gate e-bits 4..7 ----
    {
        u32 tp = (((u32)tid >> 4) << 8) | ((u32)tid & 15u);
        u32 Gtp = globOf(tp, bb);
#pragma unroll
        for (int m = 0; m < 16; m++) {
            const float4* p = (const float4*)&g_buf0[Gtp + ((u32)m << 15)];
            float4 v = *p;
            RE[m] = pk2(v.x, v.z); IM[m] = pk2(v.y, v.w);
        }
    }
    __syncthreads();  // coefficient stores visible
    gate_regs<0>(RE, IM, s_gate + (10 - 4) * 12);
    gate_regs<1>(RE, IM, s_gate + (10 - 5) * 12);
    gate_regs<2>(RE, IM, s_gate + (10 - 6) * 12);
    gate_regs<3>(RE, IM, s_gate + (10 - 7) * 12);
    sts16<4, IMOFF>(RE, IM, s_base, tid);
    __syncthreads();
    // ---- round 1: S=0 window, gate e-bits 1..3 ----
    lds16<0, IMOFF>(RE, IM, s_base, tid);
    gate_regs<1>(RE, IM, s_gate + (10 - 1) * 12);
    gate_regs<2>(RE, IM, s_gate + (10 - 2) * 12);
    gate_regs<3>(RE, IM, s_gate + (10 - 3) * 12);
    sts16<0, IMOFF>(RE, IM, s_base, tid);
    __syncthreads();
    // ---- round 2: S=7 window (e = m<<7 | tid), gate e-bits 8..10 ----
    lds16<7, IMOFF>(RE, IM, s_base, tid);
    gate_regs<1>(RE, IM, s_gate + (10 - 8) * 12);
    gate_regs<2>(RE, IM, s_gate + (10 - 9) * 12);
    gate_regs<3>(RE, IM, s_gate + (10 - 10) * 12);
    if (!LAST) {
        u32 Gt = globOf((u32)tid, bb);
#pragma unroll
        for (int m = 0; m < 16; m++) {
            float4 v; v.x = plo(RE[m]); v.y = plo(IM[m]); v.z = phi(RE[m]); v.w = phi(IM[m]);
            *(float4*)&g_buf1[Gt + ((u32)m << 18)] = v;  // e=m<<7|tid -> glob stride m<<18
        }
    }
}

__global__ void __launch_bounds__(128) k_passB(int layer) {
    __shared__ float smem[8192];   // 32KB
    __shared__ u64 s_gate[264];
    u64 RE[16], IM[16];
    passB_body<0>(layer, (char*)smem, s_gate, threadIdx.x, blockIdx.x, RE, IM);
}

// Final pass B (layer 3): fold the last CNOT permutation into the basis index and
// reduce <Z_q> directly; final state is never written.
__global__ void __launch_bounds__(128) k_passB_last() {
    __shared__ float smem[8192];
    __shared__ u64 s_gate[264];
    __shared__ float s_part[NQ * 4];
    int tid = threadIdx.x; u32 bb = blockIdx.x;
    u64 RE[16], IM[16];
    passB_body<1>(3, (char*)smem, s_gate, tid, bb, RE, IM);

    float acc[NQ];
#pragma unroll
    for (int q = 0; q < NQ; q++) acc[q] = 0.f;
    u32 Gt = globOf((u32)tid, bb);
#pragma unroll
    for (int m = 0; m < 16; m++) {
        u64 P = pfma(RE[m], RE[m], pmul(IM[m], IM[m]));   // (p0, p1) packed
        float p0 = plo(P), p1 = phi(P);
        float s = p0 + p1, d = p0 - p1;
        u32 G = Gt + ((u32)m << 18);
        u32 x = G;                  // forward CNOT-chain permutation (suffix xor)
        x ^= x >> 1; x ^= x >> 2; x ^= x >> 4; x ^= x >> 8; x ^= x >> 16;
#pragma unroll
        for (int q = 0; q < 21; q++)
            acc[q] += ((x >> (21 - q)) & 1u) ? -s : s;
        acc[21] += (x & 1u) ? -d : d;   // partner amp has x^1: wire-21 sign flips
    }
#pragma unroll
    for (int q = 0; q < NQ; q++) {
        float v = acc[q];
#pragma unroll
        for (int o = 16; o > 0; o >>= 1) v += __shfl_down_sync(0xffffffffu, v, o);
        if ((tid & 31) == 0) s_part[q * 4 + (tid >> 5)] = v;
    }
    __syncthreads();
    if (tid < NQ) {
        float s = s_part[tid * 4] + s_part[tid * 4 + 1] + s_part[tid * 4 + 2] + s_part[tid * 4 + 3];
        atomicAdd(&g_acc[tid], s);
    }
}

extern "C" void kernel_launch(void* const* d_in, const int* in_sizes, int n_in,
                              void* d_out, int out_size) {
    const float* params = (const float*)d_in[0];
    const float* sre = (const float*)d_in[1];
    const float* sim = (const float*)d_in[2];
    float* out = (float*)d_out;

    cudaFuncSetAttribute(k_passA0, cudaFuncAttributeMaxDynamicSharedMemorySize, 65536);
    cudaFuncSetAttribute(k_passAg, cudaFuncAttributeMaxDynamicSharedMemorySize, 65536);

    k_gates<<<1, 128>>>(params);
    k_passA0<<<512, 256, 65536>>>(sre, sim);
    k_passB<<<1024, 128>>>(0);
    for (int l = 1; l < 4; l++) {
        k_passAg<<<512, 256, 65536>>>(l);
        if (l < 3) k_passB<<<1024, 128>>>(l);
        else       k_passB_last<<<1024, 128>>>();
    }
    k_final<<<1, 32>>>(out);
}